// round 14
// baseline (speedup 1.0000x reference)
#include <cuda_runtime.h>
#include <cuda_fp16.h>
#include <cstdint>

#define NN 50000
#define EE 1600000
#define HH 128
#define OUTD 64
#define BN_EPS 1e-5f
#define CAP 128   // per-node bucket capacity; P(Poisson(32) > 128) ~ 1e-41

// ---------------- device scratch (static, no allocation) ----------------
__device__ int    g_cnt[NN];
__device__ int    g_bkt[(size_t)NN * CAP];
__device__ __half g_xh [(size_t)NN * HH];   // x in fp16
__device__ __half g_agg[(size_t)NN * HH];   // aggregated neighbors (fp16)
__device__ __half g_h  [(size_t)NN * HH];   // hidden activations (fp16)
__device__ float  g_y  [(size_t)NN * HH];   // pre-BN (fp32)
__device__ __half g_t  [(size_t)NN * OUTD]; // layer-2 Wl-transform (fp16, gathered)
__device__ float  g_s  [(size_t)NN * OUTD]; // layer-2 self branch + bias (fp32)
__device__ float  g_sum[HH];
__device__ float  g_sq [HH];
// pre-converted fp16 weights: layers 0/1: [0..127]=Wl rows, [128..255]=Wr rows; K=128 cols
__device__ __half g_w0[2 * HH * HH];
__device__ __half g_w1[2 * HH * HH];
// layer 2: rows 0..63 = Wl2, rows 64..127 = Wr2
__device__ __half g_w2[HH * HH];

// ---------------- zero counters + pre-convert weights to fp16 ----------------
__global__ void k_zero(const float* __restrict__ Wl0, const float* __restrict__ Wr0,
                       const float* __restrict__ Wl1, const float* __restrict__ Wr1,
                       const float* __restrict__ Wl2, const float* __restrict__ Wr2) {
    int i = blockIdx.x * blockDim.x + threadIdx.x;
    if (i < NN) g_cnt[i] = 0;
    if (i < HH * HH) {
        g_w0[i]           = __float2half_rn(Wl0[i]);
        g_w0[HH * HH + i] = __float2half_rn(Wr0[i]);
        g_w1[i]           = __float2half_rn(Wl1[i]);
        g_w1[HH * HH + i] = __float2half_rn(Wr1[i]);
    }
    if (i < OUTD * HH) {
        g_w2[i]             = __float2half_rn(Wl2[i]);
        g_w2[OUTD * HH + i] = __float2half_rn(Wr2[i]);
    }
}

// ---------------- fused single edge pass: x -> fp16 + bucket grouping ----------------
__global__ void k_fill(const float* __restrict__ x,
                       const int* __restrict__ src, const int* __restrict__ dst) {
    int i = blockIdx.x * blockDim.x + threadIdx.x;
    if (i < NN * HH / 4) {
        float4 v = *(const float4*)&x[(size_t)i * 4];
        __half2 h0 = __floats2half2_rn(v.x, v.y);
        __half2 h1 = __floats2half2_rn(v.z, v.w);
        uint2 u = make_uint2(*(uint32_t*)&h0, *(uint32_t*)&h1);
        *(uint2*)&g_xh[(size_t)i * 4] = u;
    }
    if (i < EE) {
        int d = dst[i];
        int p = atomicAdd(&g_cnt[d], 1);
        if (p < CAP) g_bkt[(size_t)d * CAP + p] = src[i];
    }
}

// ---------------- agg128: warp per node, half-warp per edge, uint4 loads ----------------
__global__ void __launch_bounds__(256) k_agg128(int use_h) {
    if (blockIdx.x == 0 && threadIdx.x < HH) {
        g_sum[threadIdx.x] = 0.f;
        g_sq [threadIdx.x] = 0.f;
    }
    const __half* __restrict__ xin = use_h ? g_h : g_xh;
    int gw = (blockIdx.x * 256 + threadIdx.x) >> 5;
    if (gw >= NN) return;
    int lane = threadIdx.x & 31;
    int hl = lane >> 4;
    int sl = lane & 15;
    int deg = g_cnt[gw];
    int cnt = deg < CAP ? deg : CAP;
    const int* __restrict__ row = &g_bkt[(size_t)gw * CAP];
    const __half* base = xin + sl * 8;

    float a0[8], a1[8];
    #pragma unroll
    for (int k = 0; k < 8; k++) { a0[k] = 0.f; a1[k] = 0.f; }

    for (int b = 0; b < cnt; b += 32) {
        int m = cnt - b; if (m > 32) m = 32;
        int idx = (lane < m) ? row[b + lane] : 0;
        for (int j = 0; j < m; j += 4) {
            int e0 = j + hl;
            int e1 = j + 2 + hl;
            int n0 = __shfl_sync(0xffffffffu, idx, e0 & 31);
            int n1 = __shfl_sync(0xffffffffu, idx, e1 & 31);
            if (e0 < m) {
                uint4 u = *(const uint4*)(base + (size_t)n0 * HH);
                float2 f0 = __half22float2(*(__half2*)&u.x);
                float2 f1 = __half22float2(*(__half2*)&u.y);
                float2 f2 = __half22float2(*(__half2*)&u.z);
                float2 f3 = __half22float2(*(__half2*)&u.w);
                a0[0] += f0.x; a0[1] += f0.y; a0[2] += f1.x; a0[3] += f1.y;
                a0[4] += f2.x; a0[5] += f2.y; a0[6] += f3.x; a0[7] += f3.y;
            }
            if (e1 < m) {
                uint4 u = *(const uint4*)(base + (size_t)n1 * HH);
                float2 f0 = __half22float2(*(__half2*)&u.x);
                float2 f1 = __half22float2(*(__half2*)&u.y);
                float2 f2 = __half22float2(*(__half2*)&u.z);
                float2 f3 = __half22float2(*(__half2*)&u.w);
                a1[0] += f0.x; a1[1] += f0.y; a1[2] += f1.x; a1[3] += f1.y;
                a1[4] += f2.x; a1[5] += f2.y; a1[6] += f3.x; a1[7] += f3.y;
            }
        }
    }
    #pragma unroll
    for (int k = 0; k < 8; k++) {
        float v = a0[k] + a1[k];
        v += __shfl_xor_sync(0xffffffffu, v, 16);
        a0[k] = v;
    }
    float inv = 1.f / fmaxf((float)deg, 1.f);
    if (hl == 0) {
        __half2 h0 = __floats2half2_rn(a0[0] * inv, a0[1] * inv);
        __half2 h1 = __floats2half2_rn(a0[2] * inv, a0[3] * inv);
        __half2 h2 = __floats2half2_rn(a0[4] * inv, a0[5] * inv);
        __half2 h3 = __floats2half2_rn(a0[6] * inv, a0[7] * inv);
        uint4 u = make_uint4(*(uint32_t*)&h0, *(uint32_t*)&h1,
                             *(uint32_t*)&h2, *(uint32_t*)&h3);
        *(uint4*)&g_agg[(size_t)gw * HH + sl * 8] = u;
    }
}

// ---------------- agg64: warp per node, quarter-warp per edge ----------------
__global__ void __launch_bounds__(256) k_agg64_add(float* __restrict__ out) {
    int gw = (blockIdx.x * 256 + threadIdx.x) >> 5;
    if (gw >= NN) return;
    int lane = threadIdx.x & 31;
    int ql = lane >> 3;
    int sl = lane & 7;
    int deg = g_cnt[gw];
    int cnt = deg < CAP ? deg : CAP;
    const int* __restrict__ row = &g_bkt[(size_t)gw * CAP];
    const __half* base = g_t + sl * 8;

    float a0[8], a1[8];
    #pragma unroll
    for (int k = 0; k < 8; k++) { a0[k] = 0.f; a1[k] = 0.f; }

    for (int b = 0; b < cnt; b += 32) {
        int m = cnt - b; if (m > 32) m = 32;
        int idx = (lane < m) ? row[b + lane] : 0;
        for (int j = 0; j < m; j += 8) {
            int e0 = j + ql;
            int e1 = j + 4 + ql;
            int n0 = __shfl_sync(0xffffffffu, idx, e0 & 31);
            int n1 = __shfl_sync(0xffffffffu, idx, e1 & 31);
            if (e0 < m) {
                uint4 u = *(const uint4*)(base + (size_t)n0 * OUTD);
                float2 f0 = __half22float2(*(__half2*)&u.x);
                float2 f1 = __half22float2(*(__half2*)&u.y);
                float2 f2 = __half22float2(*(__half2*)&u.z);
                float2 f3 = __half22float2(*(__half2*)&u.w);
                a0[0] += f0.x; a0[1] += f0.y; a0[2] += f1.x; a0[3] += f1.y;
                a0[4] += f2.x; a0[5] += f2.y; a0[6] += f3.x; a0[7] += f3.y;
            }
            if (e1 < m) {
                uint4 u = *(const uint4*)(base + (size_t)n1 * OUTD);
                float2 f0 = __half22float2(*(__half2*)&u.x);
                float2 f1 = __half22float2(*(__half2*)&u.y);
                float2 f2 = __half22float2(*(__half2*)&u.z);
                float2 f3 = __half22float2(*(__half2*)&u.w);
                a1[0] += f0.x; a1[1] += f0.y; a1[2] += f1.x; a1[3] += f1.y;
                a1[4] += f2.x; a1[5] += f2.y; a1[6] += f3.x; a1[7] += f3.y;
            }
        }
    }
    #pragma unroll
    for (int k = 0; k < 8; k++) {
        float v = a0[k] + a1[k];
        v += __shfl_xor_sync(0xffffffffu, v, 8);
        v += __shfl_xor_sync(0xffffffffu, v, 16);
        a0[k] = v;
    }
    float inv = 1.f / fmaxf((float)deg, 1.f);
    if (ql == 0) {
        const float* sp = &g_s[(size_t)gw * OUTD + sl * 8];
        float4 r0 = *(const float4*)sp;
        float4 r1 = *(const float4*)(sp + 4);
        float4 o0 = make_float4(a0[0] * inv + r0.x, a0[1] * inv + r0.y,
                                a0[2] * inv + r0.z, a0[3] * inv + r0.w);
        float4 o1 = make_float4(a0[4] * inv + r1.x, a0[5] * inv + r1.y,
                                a0[6] * inv + r1.z, a0[7] * inv + r1.w);
        float* op = &out[(size_t)gw * OUTD + sl * 8];
        *(float4*)op = o0;
        *(float4*)(op + 4) = o1;
    }
}

// ---------------- fp16 mma.sync GEMM, 128x64 tiles, double-buffered ----------------
__device__ __forceinline__ void mma_16x8x16(float* c, const uint32_t* a, const uint32_t* b) {
    asm volatile(
        "mma.sync.aligned.m16n8k16.row.col.f32.f16.f16.f32 "
        "{%0,%1,%2,%3}, {%4,%5,%6,%7}, {%8,%9}, {%0,%1,%2,%3};"
        : "+f"(c[0]), "+f"(c[1]), "+f"(c[2]), "+f"(c[3])
        : "r"(a[0]), "r"(a[1]), "r"(a[2]), "r"(a[3]), "r"(b[0]), "r"(b[1]));
}

// Block: 256 threads = 8 warps (4 row x 2 col), tile 128x64, gridDim.y=2 picks N-half.
// Layers 0/1 (KCH=8, L2=false): g_y[:, nb*64:+64] = [g_agg | A2h] @ Wh-half^T + b, fused BN stats
// Layer  2  (KCH=4, L2=true):   nb=0 -> g_t (fp16, Wl2), nb=1 -> g_s (fp32, Wr2 + b2)
template <int KCH, bool L2>
__global__ void __launch_bounds__(256, 3)
k_gemm_mma(int use_h, const __half* __restrict__ Wh, const float* __restrict__ bias)
{
    constexpr int BK = 32, LDS_ = BK + 8;   // halves

    __shared__ __half As[2][128 * LDS_];
    __shared__ __half Bs[2][64 * LDS_];
    __shared__ float sbias[OUTD];
    __shared__ float ssum[OUTD], ssq[OUTD];

    const __half* __restrict__ A2h = use_h ? g_h : g_xh;

    int tid = threadIdx.x;
    int wid = tid >> 5, lane = tid & 31;
    int wm = (wid & 3) * 32;        // warp row offset (4 groups)
    int wn = (wid >> 2) * 32;       // warp col offset (2 groups)
    int gid = lane >> 2;
    int tq  = lane & 3;
    int rowbase = blockIdx.x * 128;
    int nb = blockIdx.y;            // 0/1: N-half

    if (tid < OUTD) {
        if (L2) sbias[tid] = nb ? bias[tid] : 0.f;
        else    sbias[tid] = bias[nb * OUTD + tid];
        ssum[tid] = 0.f; ssq[tid] = 0.f;
    }

    float c[2][4][4];
    #pragma unroll
    for (int i = 0; i < 2; i++)
        #pragma unroll
        for (int j = 0; j < 4; j++)
            #pragma unroll
            for (int k = 0; k < 4; k++) c[i][j][k] = 0.f;

    int lr = tid >> 3;              // 0..31 (load row)
    int lk = (tid & 7) * 4;         // 0,4,...,28 (load k, halves)

    uint2 areg[4];
    uint2 breg[2];

    auto gload = [&](int kc) {
        const __half* __restrict__ Asrc;
        int kb;
        if (L2) { Asrc = A2h; kb = kc * BK; }
        else    { Asrc = (kc < 4) ? g_agg : A2h; kb = (kc & 3) * BK; }
        #pragma unroll
        for (int it = 0; it < 4; it++) {
            int r = rowbase + lr + it * 32;
            areg[it] = make_uint2(0u, 0u);
            if (r < NN) areg[it] = *(const uint2*)&Asrc[(size_t)r * HH + kb + lk];
        }
        int wbase = L2 ? 0 : ((kc < 4) ? 0 : HH * HH);
        #pragma unroll
        for (int it = 0; it < 2; it++) {
            int n = lr + it * 32;                 // 0..63 local
            breg[it] = *(const uint2*)&Wh[wbase + (size_t)(nb * OUTD + n) * HH + kb + lk];
        }
    };
    auto sstore = [&](int buf) {
        #pragma unroll
        for (int it = 0; it < 4; it++)
            *(uint2*)&As[buf][(lr + it * 32) * LDS_ + lk] = areg[it];
        #pragma unroll
        for (int it = 0; it < 2; it++)
            *(uint2*)&Bs[buf][(lr + it * 32) * LDS_ + lk] = breg[it];
    };

    gload(0);
    sstore(0);
    __syncthreads();

    for (int kc = 0; kc < KCH; kc++) {
        int buf = kc & 1;
        if (kc + 1 < KCH) gload(kc + 1);

        #pragma unroll
        for (int ks = 0; ks < BK / 16; ks++) {
            int k0 = ks * 16;
            uint32_t a[2][4], b[4][2];
            #pragma unroll
            for (int mi = 0; mi < 2; mi++) {
                const __half* p = &As[buf][(wm + mi * 16 + gid) * LDS_ + k0 + tq * 2];
                a[mi][0] = *(const uint32_t*)p;
                a[mi][1] = *(const uint32_t*)(p + 8 * LDS_);
                a[mi][2] = *(const uint32_t*)(p + 8);
                a[mi][3] = *(const uint32_t*)(p + 8 * LDS_ + 8);
            }
            #pragma unroll
            for (int nj = 0; nj < 4; nj++) {
                const __half* p = &Bs[buf][(wn + nj * 8 + gid) * LDS_ + k0 + tq * 2];
                b[nj][0] = *(const uint32_t*)p;
                b[nj][1] = *(const uint32_t*)(p + 8);
            }
            #pragma unroll
            for (int mi = 0; mi < 2; mi++)
                #pragma unroll
                for (int nj = 0; nj < 4; nj++)
                    mma_16x8x16(c[mi][nj], a[mi], b[nj]);
        }

        if (kc + 1 < KCH) sstore(buf ^ 1);
        __syncthreads();
    }

    // epilogue
    if (L2) {
        #pragma unroll
        for (int mi = 0; mi < 2; mi++) {
            int r0 = rowbase + wm + mi * 16 + gid;
            int r1 = r0 + 8;
            #pragma unroll
            for (int nj = 0; nj < 4; nj++) {
                int col = wn + nj * 8 + tq * 2;     // 0..63 local
                if (nb == 0) {
                    if (r0 < NN)
                        *(__half2*)&g_t[(size_t)r0 * OUTD + col] =
                            __floats2half2_rn(c[mi][nj][0], c[mi][nj][1]);
                    if (r1 < NN)
                        *(__half2*)&g_t[(size_t)r1 * OUTD + col] =
                            __floats2half2_rn(c[mi][nj][2], c[mi][nj][3]);
                } else {
                    float bx = sbias[col], by = sbias[col + 1];
                    if (r0 < NN)
                        *(float2*)&g_s[(size_t)r0 * OUTD + col] =
                            make_float2(c[mi][nj][0] + bx, c[mi][nj][1] + by);
                    if (r1 < NN)
                        *(float2*)&g_s[(size_t)r1 * OUTD + col] =
                            make_float2(c[mi][nj][2] + bx, c[mi][nj][3] + by);
                }
            }
        }
    } else {
        float ls[8], lq[8];
        #pragma unroll
        for (int j = 0; j < 8; j++) { ls[j] = 0.f; lq[j] = 0.f; }

        #pragma unroll
        for (int mi = 0; mi < 2; mi++) {
            int r0 = rowbase + wm + mi * 16 + gid;
            int r1 = r0 + 8;
            #pragma unroll
            for (int nj = 0; nj < 4; nj++) {
                int col = wn + nj * 8 + tq * 2;     // local
                float bx = sbias[col], by = sbias[col + 1];
                int gcol = nb * OUTD + col;
                if (r0 < NN) {
                    float vx = c[mi][nj][0] + bx, vy = c[mi][nj][1] + by;
                    *(float2*)&g_y[(size_t)r0 * HH + gcol] = make_float2(vx, vy);
                    ls[nj * 2] += vx; lq[nj * 2] += vx * vx;
                    ls[nj * 2 + 1] += vy; lq[nj * 2 + 1] += vy * vy;
                }
                if (r1 < NN) {
                    float vx = c[mi][nj][2] + bx, vy = c[mi][nj][3] + by;
                    *(float2*)&g_y[(size_t)r1 * HH + gcol] = make_float2(vx, vy);
                    ls[nj * 2] += vx; lq[nj * 2] += vx * vx;
                    ls[nj * 2 + 1] += vy; lq[nj * 2 + 1] += vy * vy;
                }
            }
        }

        #pragma unroll
        for (int nj = 0; nj < 4; nj++) {
            int col = wn + nj * 8 + tq * 2;
            atomicAdd(&ssum[col],     ls[nj * 2]);
            atomicAdd(&ssq [col],     lq[nj * 2]);
            atomicAdd(&ssum[col + 1], ls[nj * 2 + 1]);
            atomicAdd(&ssq [col + 1], lq[nj * 2 + 1]);
        }
        __syncthreads();
        if (tid < OUTD) {
            atomicAdd(&g_sum[nb * OUTD + tid], ssum[tid]);
            atomicAdd(&g_sq [nb * OUTD + tid], ssq [tid]);
        }
    }
}

// ---------------- BN apply + ReLU: g_y (fp32) -> g_h (fp16) ----------------
__global__ void k_bn4(const float* __restrict__ gamma, const float* __restrict__ beta) {
    int i = blockIdx.x * blockDim.x + threadIdx.x;
    if (i >= NN * HH / 4) return;
    int o = (i & 31) * 4;
    const float invN = 1.0f / (float)NN;
    float4 y = *(const float4*)&g_y[(size_t)i * 4];
    float r0, r1, r2, r3;
    float mu, var, s;
    mu = g_sum[o + 0] * invN; var = g_sq[o + 0] * invN - mu * mu; s = rsqrtf(var + BN_EPS) * gamma[o + 0];
    r0 = fmaxf((y.x - mu) * s + beta[o + 0], 0.f);
    mu = g_sum[o + 1] * invN; var = g_sq[o + 1] * invN - mu * mu; s = rsqrtf(var + BN_EPS) * gamma[o + 1];
    r1 = fmaxf((y.y - mu) * s + beta[o + 1], 0.f);
    mu = g_sum[o + 2] * invN; var = g_sq[o + 2] * invN - mu * mu; s = rsqrtf(var + BN_EPS) * gamma[o + 2];
    r2 = fmaxf((y.z - mu) * s + beta[o + 2], 0.f);
    mu = g_sum[o + 3] * invN; var = g_sq[o + 3] * invN - mu * mu; s = rsqrtf(var + BN_EPS) * gamma[o + 3];
    r3 = fmaxf((y.w - mu) * s + beta[o + 3], 0.f);
    __half2 h0 = __floats2half2_rn(r0, r1);
    __half2 h1 = __floats2half2_rn(r2, r3);
    uint2 u = make_uint2(*(uint32_t*)&h0, *(uint32_t*)&h1);
    *(uint2*)&g_h[(size_t)i * 4] = u;
}

// ---------------- launch ----------------
extern "C" void kernel_launch(void* const* d_in, const int* in_sizes, int n_in,
                              void* d_out, int out_size)
{
    const float* x   = (const float*)d_in[0];
    const int*   ei  = (const int*)d_in[1];
    const int*   src = ei;
    const int*   dst = ei + EE;
    const float* Wl0 = (const float*)d_in[2];
    const float* Wr0 = (const float*)d_in[3];
    const float* b0  = (const float*)d_in[4];
    const float* g0  = (const float*)d_in[5];
    const float* be0 = (const float*)d_in[6];
    const float* Wl1 = (const float*)d_in[7];
    const float* Wr1 = (const float*)d_in[8];
    const float* b1  = (const float*)d_in[9];
    const float* g1  = (const float*)d_in[10];
    const float* be1 = (const float*)d_in[11];
    const float* Wl2 = (const float*)d_in[12];
    const float* Wr2 = (const float*)d_in[13];
    const float* b2  = (const float*)d_in[14];
    float* out = (float*)d_out;

    const int TPB = 256;
    const int gE  = (EE + TPB - 1) / TPB;
    const int gN  = (NN + TPB - 1) / TPB;
    const int gG  = (NN + 127) / 128;
    const int gW  = (NN * 32 + TPB - 1) / TPB;
    const int gBN = (NN * HH / 4 + TPB - 1) / TPB;

    __half* w0; cudaGetSymbolAddress((void**)&w0, g_w0);
    __half* w1; cudaGetSymbolAddress((void**)&w1, g_w1);
    __half* w2; cudaGetSymbolAddress((void**)&w2, g_w2);

    dim3 gridG(gG, 2);

    // bucket grouping build + fp16 weight pre-conversion; 10 launches total
    k_zero<<<gN, TPB>>>(Wl0, Wr0, Wl1, Wr1, Wl2, Wr2);
    k_fill<<<gE, TPB>>>(x, src, dst);

    // layer 0
    k_agg128<<<gW, TPB>>>(0);
    k_gemm_mma<8, false><<<gridG, TPB>>>(0, w0, b0);
    k_bn4<<<gBN, TPB>>>(g0, be0);

    // layer 1
    k_agg128<<<gW, TPB>>>(1);
    k_gemm_mma<8, false><<<gridG, TPB>>>(1, w1, b1);
    k_bn4<<<gBN, TPB>>>(g1, be1);

    // layer 2: transform first (split dual GEMM), then fp16 64-dim aggregate + add
    k_gemm_mma<4, true><<<gridG, TPB>>>(1, w2, b2);
    k_agg64_add<<<gW, TPB>>>(out);
}

// round 15
// speedup vs baseline: 1.0899x; 1.0899x over previous
#include <cuda_runtime.h>
#include <cuda_fp16.h>
#include <cstdint>

#define NN 50000
#define EE 1600000
#define HH 128
#define OUTD 64
#define BN_EPS 1e-5f
#define CAP 128   // per-node bucket capacity; P(Poisson(32) > 128) ~ 1e-41

// ---------------- device scratch (static, no allocation) ----------------
__device__ int    g_cnt[NN];
__device__ int    g_bkt[(size_t)NN * CAP];
__device__ __half g_xh [(size_t)NN * HH];   // x in fp16
__device__ __half g_agg[(size_t)NN * HH];   // aggregated neighbors (fp16)
__device__ __half g_h  [(size_t)NN * HH];   // hidden activations (fp16)
__device__ float  g_y  [(size_t)NN * HH];   // pre-BN (fp32)
__device__ __half g_t  [(size_t)NN * OUTD]; // layer-2 Wl-transform (fp16, gathered)
__device__ float  g_s  [(size_t)NN * OUTD]; // layer-2 self branch + bias (fp32)
__device__ float  g_sum[HH];
__device__ float  g_sq [HH];
// pre-converted fp16 weights: layers 0/1: rows [0..127]=Wl, [128..255]=Wr; K=128 cols
__device__ __half g_w0[2 * HH * HH];
__device__ __half g_w1[2 * HH * HH];
// layer 2: rows 0..63 = Wl2, rows 64..127 = Wr2
__device__ __half g_w2[HH * HH];

// ---------------- zero counters + pre-convert weights to fp16 ----------------
__global__ void k_zero(const float* __restrict__ Wl0, const float* __restrict__ Wr0,
                       const float* __restrict__ Wl1, const float* __restrict__ Wr1,
                       const float* __restrict__ Wl2, const float* __restrict__ Wr2) {
    int i = blockIdx.x * blockDim.x + threadIdx.x;
    if (i < NN) g_cnt[i] = 0;
    if (i < HH * HH) {
        g_w0[i]           = __float2half_rn(Wl0[i]);
        g_w0[HH * HH + i] = __float2half_rn(Wr0[i]);
        g_w1[i]           = __float2half_rn(Wl1[i]);
        g_w1[HH * HH + i] = __float2half_rn(Wr1[i]);
    }
    if (i < OUTD * HH) {
        g_w2[i]             = __float2half_rn(Wl2[i]);
        g_w2[OUTD * HH + i] = __float2half_rn(Wr2[i]);
    }
}

// ---------------- fused single edge pass: x -> fp16 + bucket grouping ----------------
__global__ void k_fill(const float* __restrict__ x,
                       const int* __restrict__ src, const int* __restrict__ dst) {
    int i = blockIdx.x * blockDim.x + threadIdx.x;
    if (i < NN * HH / 4) {
        float4 v = *(const float4*)&x[(size_t)i * 4];
        __half2 h0 = __floats2half2_rn(v.x, v.y);
        __half2 h1 = __floats2half2_rn(v.z, v.w);
        uint2 u = make_uint2(*(uint32_t*)&h0, *(uint32_t*)&h1);
        *(uint2*)&g_xh[(size_t)i * 4] = u;
    }
    if (i < EE) {
        int d = dst[i];
        int p = atomicAdd(&g_cnt[d], 1);
        if (p < CAP) g_bkt[(size_t)d * CAP + p] = src[i];
    }
}

// ---------------- agg128: warp per node, half-warp per edge, uint4 loads ----------------
__global__ void __launch_bounds__(256) k_agg128(int use_h) {
    if (blockIdx.x == 0 && threadIdx.x < HH) {
        g_sum[threadIdx.x] = 0.f;
        g_sq [threadIdx.x] = 0.f;
    }
    const __half* __restrict__ xin = use_h ? g_h : g_xh;
    int gw = (blockIdx.x * 256 + threadIdx.x) >> 5;
    if (gw >= NN) return;
    int lane = threadIdx.x & 31;
    int hl = lane >> 4;
    int sl = lane & 15;
    int deg = g_cnt[gw];
    int cnt = deg < CAP ? deg : CAP;
    const int* __restrict__ row = &g_bkt[(size_t)gw * CAP];
    const __half* base = xin + sl * 8;

    float a0[8], a1[8];
    #pragma unroll
    for (int k = 0; k < 8; k++) { a0[k] = 0.f; a1[k] = 0.f; }

    for (int b = 0; b < cnt; b += 32) {
        int m = cnt - b; if (m > 32) m = 32;
        int idx = (lane < m) ? row[b + lane] : 0;
        for (int j = 0; j < m; j += 4) {
            int e0 = j + hl;
            int e1 = j + 2 + hl;
            int n0 = __shfl_sync(0xffffffffu, idx, e0 & 31);
            int n1 = __shfl_sync(0xffffffffu, idx, e1 & 31);
            if (e0 < m) {
                uint4 u = *(const uint4*)(base + (size_t)n0 * HH);
                float2 f0 = __half22float2(*(__half2*)&u.x);
                float2 f1 = __half22float2(*(__half2*)&u.y);
                float2 f2 = __half22float2(*(__half2*)&u.z);
                float2 f3 = __half22float2(*(__half2*)&u.w);
                a0[0] += f0.x; a0[1] += f0.y; a0[2] += f1.x; a0[3] += f1.y;
                a0[4] += f2.x; a0[5] += f2.y; a0[6] += f3.x; a0[7] += f3.y;
            }
            if (e1 < m) {
                uint4 u = *(const uint4*)(base + (size_t)n1 * HH);
                float2 f0 = __half22float2(*(__half2*)&u.x);
                float2 f1 = __half22float2(*(__half2*)&u.y);
                float2 f2 = __half22float2(*(__half2*)&u.z);
                float2 f3 = __half22float2(*(__half2*)&u.w);
                a1[0] += f0.x; a1[1] += f0.y; a1[2] += f1.x; a1[3] += f1.y;
                a1[4] += f2.x; a1[5] += f2.y; a1[6] += f3.x; a1[7] += f3.y;
            }
        }
    }
    #pragma unroll
    for (int k = 0; k < 8; k++) {
        float v = a0[k] + a1[k];
        v += __shfl_xor_sync(0xffffffffu, v, 16);
        a0[k] = v;
    }
    float inv = 1.f / fmaxf((float)deg, 1.f);
    if (hl == 0) {
        __half2 h0 = __floats2half2_rn(a0[0] * inv, a0[1] * inv);
        __half2 h1 = __floats2half2_rn(a0[2] * inv, a0[3] * inv);
        __half2 h2 = __floats2half2_rn(a0[4] * inv, a0[5] * inv);
        __half2 h3 = __floats2half2_rn(a0[6] * inv, a0[7] * inv);
        uint4 u = make_uint4(*(uint32_t*)&h0, *(uint32_t*)&h1,
                             *(uint32_t*)&h2, *(uint32_t*)&h3);
        *(uint4*)&g_agg[(size_t)gw * HH + sl * 8] = u;
    }
}

// ---------------- agg64: warp per node, quarter-warp per edge ----------------
__global__ void __launch_bounds__(256) k_agg64_add(float* __restrict__ out) {
    int gw = (blockIdx.x * 256 + threadIdx.x) >> 5;
    if (gw >= NN) return;
    int lane = threadIdx.x & 31;
    int ql = lane >> 3;
    int sl = lane & 7;
    int deg = g_cnt[gw];
    int cnt = deg < CAP ? deg : CAP;
    const int* __restrict__ row = &g_bkt[(size_t)gw * CAP];
    const __half* base = g_t + sl * 8;

    float a0[8], a1[8];
    #pragma unroll
    for (int k = 0; k < 8; k++) { a0[k] = 0.f; a1[k] = 0.f; }

    for (int b = 0; b < cnt; b += 32) {
        int m = cnt - b; if (m > 32) m = 32;
        int idx = (lane < m) ? row[b + lane] : 0;
        for (int j = 0; j < m; j += 8) {
            int e0 = j + ql;
            int e1 = j + 4 + ql;
            int n0 = __shfl_sync(0xffffffffu, idx, e0 & 31);
            int n1 = __shfl_sync(0xffffffffu, idx, e1 & 31);
            if (e0 < m) {
                uint4 u = *(const uint4*)(base + (size_t)n0 * OUTD);
                float2 f0 = __half22float2(*(__half2*)&u.x);
                float2 f1 = __half22float2(*(__half2*)&u.y);
                float2 f2 = __half22float2(*(__half2*)&u.z);
                float2 f3 = __half22float2(*(__half2*)&u.w);
                a0[0] += f0.x; a0[1] += f0.y; a0[2] += f1.x; a0[3] += f1.y;
                a0[4] += f2.x; a0[5] += f2.y; a0[6] += f3.x; a0[7] += f3.y;
            }
            if (e1 < m) {
                uint4 u = *(const uint4*)(base + (size_t)n1 * OUTD);
                float2 f0 = __half22float2(*(__half2*)&u.x);
                float2 f1 = __half22float2(*(__half2*)&u.y);
                float2 f2 = __half22float2(*(__half2*)&u.z);
                float2 f3 = __half22float2(*(__half2*)&u.w);
                a1[0] += f0.x; a1[1] += f0.y; a1[2] += f1.x; a1[3] += f1.y;
                a1[4] += f2.x; a1[5] += f2.y; a1[6] += f3.x; a1[7] += f3.y;
            }
        }
    }
    #pragma unroll
    for (int k = 0; k < 8; k++) {
        float v = a0[k] + a1[k];
        v += __shfl_xor_sync(0xffffffffu, v, 8);
        v += __shfl_xor_sync(0xffffffffu, v, 16);
        a0[k] = v;
    }
    float inv = 1.f / fmaxf((float)deg, 1.f);
    if (ql == 0) {
        const float* sp = &g_s[(size_t)gw * OUTD + sl * 8];
        float4 r0 = *(const float4*)sp;
        float4 r1 = *(const float4*)(sp + 4);
        float4 o0 = make_float4(a0[0] * inv + r0.x, a0[1] * inv + r0.y,
                                a0[2] * inv + r0.z, a0[3] * inv + r0.w);
        float4 o1 = make_float4(a0[4] * inv + r1.x, a0[5] * inv + r1.y,
                                a0[6] * inv + r1.z, a0[7] * inv + r1.w);
        float* op = &out[(size_t)gw * OUTD + sl * 8];
        *(float4*)op = o0;
        *(float4*)(op + 4) = o1;
    }
}

// ---------------- fp16 mma.sync GEMM, 128x128 tile, double-buffered (round-13 geometry) ----------------
__device__ __forceinline__ void mma_16x8x16(float* c, const uint32_t* a, const uint32_t* b) {
    asm volatile(
        "mma.sync.aligned.m16n8k16.row.col.f32.f16.f16.f32 "
        "{%0,%1,%2,%3}, {%4,%5,%6,%7}, {%8,%9}, {%0,%1,%2,%3};"
        : "+f"(c[0]), "+f"(c[1]), "+f"(c[2]), "+f"(c[3])
        : "r"(a[0]), "r"(a[1]), "r"(a[2]), "r"(a[3]), "r"(b[0]), "r"(b[1]));
}

// Block: 256 threads = 8 warps (2 row x 4 col), tile 128x128, BK=32, 2-stage pipeline.
// Layers 0/1 (KCH=8, L2=false): g_y = [g_agg | A2h] @ W^T + b (K=256), fused BN stats
// Layer  2  (KCH=4, L2=true):   cols 0-63 -> g_t (fp16), cols 64-127 -> g_s (fp32 + b2)
template <int KCH, bool L2>
__global__ void __launch_bounds__(256)
k_gemm_mma(int use_h, const __half* __restrict__ Wh, const float* __restrict__ bias)
{
    constexpr int BK = 32, LDS_ = BK + 8;   // halves

    __shared__ __half As[2][128 * LDS_];
    __shared__ __half Bs[2][128 * LDS_];
    __shared__ float sbias[HH];
    __shared__ float ssum[HH], ssq[HH];

    const __half* __restrict__ A2h = use_h ? g_h : g_xh;

    int tid = threadIdx.x;
    int wid = tid >> 5, lane = tid & 31;
    int wm = (wid & 1) * 64;
    int wn = (wid >> 1) * 32;
    int gid = lane >> 2;
    int tq  = lane & 3;
    int rowbase = blockIdx.x * 128;

    if (tid < HH) {
        if (L2) sbias[tid] = (tid >= OUTD) ? bias[tid - OUTD] : 0.f;
        else    sbias[tid] = bias[tid];
        ssum[tid] = 0.f; ssq[tid] = 0.f;
    }

    float c[4][4][4];
    #pragma unroll
    for (int i = 0; i < 4; i++)
        #pragma unroll
        for (int j = 0; j < 4; j++)
            #pragma unroll
            for (int k = 0; k < 4; k++) c[i][j][k] = 0.f;

    int lr = tid >> 3;              // 0..31 (load row)
    int lk = (tid & 7) * 4;         // 0,4,...,28 (load k, halves)

    uint2 areg[4];
    uint2 breg[4];

    auto gload = [&](int kc) {
        const __half* __restrict__ Asrc;
        int kb;
        if (L2) { Asrc = A2h; kb = kc * BK; }
        else    { Asrc = (kc < 4) ? g_agg : A2h; kb = (kc & 3) * BK; }
        #pragma unroll
        for (int it = 0; it < 4; it++) {
            int r = rowbase + lr + it * 32;
            areg[it] = make_uint2(0u, 0u);
            if (r < NN) areg[it] = *(const uint2*)&Asrc[(size_t)r * HH + kb + lk];
        }
        int wbase = L2 ? 0 : ((kc < 4) ? 0 : HH * HH);
        #pragma unroll
        for (int it = 0; it < 4; it++) {
            int n = lr + it * 32;
            breg[it] = *(const uint2*)&Wh[wbase + (size_t)n * HH + kb + lk];
        }
    };
    auto sstore = [&](int buf) {
        #pragma unroll
        for (int it = 0; it < 4; it++)
            *(uint2*)&As[buf][(lr + it * 32) * LDS_ + lk] = areg[it];
        #pragma unroll
        for (int it = 0; it < 4; it++)
            *(uint2*)&Bs[buf][(lr + it * 32) * LDS_ + lk] = breg[it];
    };

    gload(0);
    sstore(0);
    __syncthreads();

    for (int kc = 0; kc < KCH; kc++) {
        int buf = kc & 1;
        if (kc + 1 < KCH) gload(kc + 1);

        #pragma unroll
        for (int ks = 0; ks < BK / 16; ks++) {
            int k0 = ks * 16;
            uint32_t a[4][4], b[4][2];
            #pragma unroll
            for (int mi = 0; mi < 4; mi++) {
                const __half* p = &As[buf][(wm + mi * 16 + gid) * LDS_ + k0 + tq * 2];
                a[mi][0] = *(const uint32_t*)p;
                a[mi][1] = *(const uint32_t*)(p + 8 * LDS_);
                a[mi][2] = *(const uint32_t*)(p + 8);
                a[mi][3] = *(const uint32_t*)(p + 8 * LDS_ + 8);
            }
            #pragma unroll
            for (int nj = 0; nj < 4; nj++) {
                const __half* p = &Bs[buf][(wn + nj * 8 + gid) * LDS_ + k0 + tq * 2];
                b[nj][0] = *(const uint32_t*)p;
                b[nj][1] = *(const uint32_t*)(p + 8);
            }
            #pragma unroll
            for (int mi = 0; mi < 4; mi++)
                #pragma unroll
                for (int nj = 0; nj < 4; nj++)
                    mma_16x8x16(c[mi][nj], a[mi], b[nj]);
        }

        if (kc + 1 < KCH) sstore(buf ^ 1);
        __syncthreads();
    }

    // epilogue
    if (L2) {
        #pragma unroll
        for (int mi = 0; mi < 4; mi++) {
            int r0 = rowbase + wm + mi * 16 + gid;
            int r1 = r0 + 8;
            #pragma unroll
            for (int nj = 0; nj < 4; nj++) {
                int col = wn + nj * 8 + tq * 2;
                if (col < OUTD) {
                    if (r0 < NN)
                        *(__half2*)&g_t[(size_t)r0 * OUTD + col] =
                            __floats2half2_rn(c[mi][nj][0], c[mi][nj][1]);
                    if (r1 < NN)
                        *(__half2*)&g_t[(size_t)r1 * OUTD + col] =
                            __floats2half2_rn(c[mi][nj][2], c[mi][nj][3]);
                } else {
                    int sc = col - OUTD;
                    float bx = sbias[col], by = sbias[col + 1];
                    if (r0 < NN)
                        *(float2*)&g_s[(size_t)r0 * OUTD + sc] =
                            make_float2(c[mi][nj][0] + bx, c[mi][nj][1] + by);
                    if (r1 < NN)
                        *(float2*)&g_s[(size_t)r1 * OUTD + sc] =
                            make_float2(c[mi][nj][2] + bx, c[mi][nj][3] + by);
                }
            }
        }
    } else {
        float ls[8], lq[8];
        #pragma unroll
        for (int j = 0; j < 8; j++) { ls[j] = 0.f; lq[j] = 0.f; }

        #pragma unroll
        for (int mi = 0; mi < 4; mi++) {
            int r0 = rowbase + wm + mi * 16 + gid;
            int r1 = r0 + 8;
            #pragma unroll
            for (int nj = 0; nj < 4; nj++) {
                int col = wn + nj * 8 + tq * 2;
                float bx = sbias[col], by = sbias[col + 1];
                if (r0 < NN) {
                    float vx = c[mi][nj][0] + bx, vy = c[mi][nj][1] + by;
                    *(float2*)&g_y[(size_t)r0 * HH + col] = make_float2(vx, vy);
                    ls[nj * 2] += vx; lq[nj * 2] += vx * vx;
                    ls[nj * 2 + 1] += vy; lq[nj * 2 + 1] += vy * vy;
                }
                if (r1 < NN) {
                    float vx = c[mi][nj][2] + bx, vy = c[mi][nj][3] + by;
                    *(float2*)&g_y[(size_t)r1 * HH + col] = make_float2(vx, vy);
                    ls[nj * 2] += vx; lq[nj * 2] += vx * vx;
                    ls[nj * 2 + 1] += vy; lq[nj * 2 + 1] += vy * vy;
                }
            }
        }

        #pragma unroll
        for (int nj = 0; nj < 4; nj++) {
            int col = wn + nj * 8 + tq * 2;
            atomicAdd(&ssum[col],     ls[nj * 2]);
            atomicAdd(&ssq [col],     lq[nj * 2]);
            atomicAdd(&ssum[col + 1], ls[nj * 2 + 1]);
            atomicAdd(&ssq [col + 1], lq[nj * 2 + 1]);
        }
        __syncthreads();
        if (tid < HH) {
            atomicAdd(&g_sum[tid], ssum[tid]);
            atomicAdd(&g_sq [tid], ssq [tid]);
        }
    }
}

// ---------------- BN apply + ReLU: g_y (fp32) -> g_h (fp16) ----------------
__global__ void k_bn4(const float* __restrict__ gamma, const float* __restrict__ beta) {
    int i = blockIdx.x * blockDim.x + threadIdx.x;
    if (i >= NN * HH / 4) return;
    int o = (i & 31) * 4;
    const float invN = 1.0f / (float)NN;
    float4 y = *(const float4*)&g_y[(size_t)i * 4];
    float r0, r1, r2, r3;
    float mu, var, s;
    mu = g_sum[o + 0] * invN; var = g_sq[o + 0] * invN - mu * mu; s = rsqrtf(var + BN_EPS) * gamma[o + 0];
    r0 = fmaxf((y.x - mu) * s + beta[o + 0], 0.f);
    mu = g_sum[o + 1] * invN; var = g_sq[o + 1] * invN - mu * mu; s = rsqrtf(var + BN_EPS) * gamma[o + 1];
    r1 = fmaxf((y.y - mu) * s + beta[o + 1], 0.f);
    mu = g_sum[o + 2] * invN; var = g_sq[o + 2] * invN - mu * mu; s = rsqrtf(var + BN_EPS) * gamma[o + 2];
    r2 = fmaxf((y.z - mu) * s + beta[o + 2], 0.f);
    mu = g_sum[o + 3] * invN; var = g_sq[o + 3] * invN - mu * mu; s = rsqrtf(var + BN_EPS) * gamma[o + 3];
    r3 = fmaxf((y.w - mu) * s + beta[o + 3], 0.f);
    __half2 h0 = __floats2half2_rn(r0, r1);
    __half2 h1 = __floats2half2_rn(r2, r3);
    uint2 u = make_uint2(*(uint32_t*)&h0, *(uint32_t*)&h1);
    *(uint2*)&g_h[(size_t)i * 4] = u;
}

// ---------------- launch ----------------
extern "C" void kernel_launch(void* const* d_in, const int* in_sizes, int n_in,
                              void* d_out, int out_size)
{
    const float* x   = (const float*)d_in[0];
    const int*   ei  = (const int*)d_in[1];
    const int*   src = ei;
    const int*   dst = ei + EE;
    const float* Wl0 = (const float*)d_in[2];
    const float* Wr0 = (const float*)d_in[3];
    const float* b0  = (const float*)d_in[4];
    const float* g0  = (const float*)d_in[5];
    const float* be0 = (const float*)d_in[6];
    const float* Wl1 = (const float*)d_in[7];
    const float* Wr1 = (const float*)d_in[8];
    const float* b1  = (const float*)d_in[9];
    const float* g1  = (const float*)d_in[10];
    const float* be1 = (const float*)d_in[11];
    const float* Wl2 = (const float*)d_in[12];
    const float* Wr2 = (const float*)d_in[13];
    const float* b2  = (const float*)d_in[14];
    float* out = (float*)d_out;

    const int TPB = 256;
    const int gE  = (EE + TPB - 1) / TPB;
    const int gN  = (NN + TPB - 1) / TPB;
    const int gG  = (NN + 127) / 128;
    const int gW  = (NN * 32 + TPB - 1) / TPB;
    const int gBN = (NN * HH / 4 + TPB - 1) / TPB;

    __half* w0; cudaGetSymbolAddress((void**)&w0, g_w0);
    __half* w1; cudaGetSymbolAddress((void**)&w1, g_w1);
    __half* w2; cudaGetSymbolAddress((void**)&w2, g_w2);

    // bucket grouping build + fp16 weight pre-conversion; 10 launches total
    k_zero<<<gN, TPB>>>(Wl0, Wr0, Wl1, Wr1, Wl2, Wr2);
    k_fill<<<gE, TPB>>>(x, src, dst);

    // layer 0
    k_agg128<<<gW, TPB>>>(0);
    k_gemm_mma<8, false><<<gG, TPB>>>(0, w0, b0);
    k_bn4<<<gBN, TPB>>>(g0, be0);

    // layer 1
    k_agg128<<<gW, TPB>>>(1);
    k_gemm_mma<8, false><<<gG, TPB>>>(1, w1, b1);
    k_bn4<<<gBN, TPB>>>(g1, be1);

    // layer 2: transform first (N-concat dual GEMM), then fp16 64-dim aggregate + add
    k_gemm_mma<4, true><<<gG, TPB>>>(1, w2, b2);
    k_agg64_add<<<gW, TPB>>>(out);
}